// round 16
// baseline (speedup 1.0000x reference)
#include <cuda_runtime.h>
#include <cuda_bf16.h>
#include <cstdint>

// Problem constants
#define BB   8
#define NN   4096
#define MM   1024
#define CIN  32
#define KNB  64
#define NEGV (-1e10f)
#define R2F  (0.04f)

// Scratch (device globals: allocation-free)
__device__ int   g_fps[BB * MM];
__device__ float g_t[(size_t)BB * NN * 64];
__device__ int   g_nbr[(size_t)BB * MM * KNB];

// Conv weights in constant memory (uniform access -> constant port, not smem)
__constant__ float c_W2[64 * 64];
__constant__ float c_W3[64 * 128];
__constant__ float c_W1p[192];
__constant__ float c_b1[64];
__constant__ float c_b2[64];
__constant__ float c_b3[128];

typedef unsigned long long ull;

// ---------------- helpers: packed f32x2 ----------------
__device__ __forceinline__ ull pack2(float lo, float hi) {
    ull r; asm("mov.b64 %0, {%1, %2};" : "=l"(r) : "f"(lo), "f"(hi)); return r;
}
__device__ __forceinline__ ull bc2(float v) {
    ull r; asm("mov.b64 %0, {%1, %1};" : "=l"(r) : "f"(v)); return r;
}
__device__ __forceinline__ void unpack2(ull v, float& lo, float& hi) {
    asm("mov.b64 {%0, %1}, %2;" : "=f"(lo), "=f"(hi) : "l"(v));
}
__device__ __forceinline__ void fma2(ull& acc, ull a, ull b) {
    asm("fma.rn.f32x2 %0, %1, %2, %0;" : "+l"(acc) : "l"(a), "l"(b));
}
__device__ __forceinline__ ull add2(ull a, ull b) {
    ull r; asm("add.rn.f32x2 %0, %1, %2;" : "=l"(r) : "l"(a), "l"(b)); return r;
}
__device__ __forceinline__ ull mul2(ull a, ull b) {
    ull r; asm("mul.rn.f32x2 %0, %1, %2;" : "=l"(r) : "l"(a), "l"(b)); return r;
}
// per-component identical to __fadd_rn(__fadd_rn(__fmul_rn,__fmul_rn),__fmul_rn)
__device__ __forceinline__ ull sqdist2(ull X, ull Y, ull Z, ull ncx, ull ncy, ull ncz) {
    ull dx = add2(X, ncx), dy = add2(Y, ncy), dz = add2(Z, ncz);
    return add2(add2(mul2(dx, dx), mul2(dy, dy)), mul2(dz, dz));
}
__device__ __forceinline__ ull umax64(ull a, ull b) { return a > b ? a : b; }

// ---------------- Kernel A: farthest point sampling (v4, unchanged) ----------------
__global__ void __launch_bounds__(256) fps_kernel(const float* __restrict__ pos) {
    extern __shared__ float sm[];
    float* sx = sm;
    float* sy = sm + NN;
    float* sz = sm + 2 * NN;
    __shared__ alignas(16) ull skey[2][8];

    const int b = blockIdx.x;
    const int tid = threadIdx.x;
    const int lane = tid & 31;
    const float* pb = pos + (size_t)b * NN * 3;

    for (int i = tid; i < NN; i += 256) {
        sx[i] = pb[i * 3 + 0];
        sy[i] = pb[i * 3 + 1];
        sz[i] = pb[i * 3 + 2];
    }
    if (tid == 0) g_fps[b * MM] = 0;
    __syncthreads();

    const int base = tid * 16;
    ull X[8], Y[8], Z[8];
#pragma unroll
    for (int j = 0; j < 8; ++j) {
        X[j] = pack2(sx[base + 2 * j], sx[base + 2 * j + 1]);
        Y[j] = pack2(sy[base + 2 * j], sy[base + 2 * j + 1]);
        Z[j] = pack2(sz[base + 2 * j], sz[base + 2 * j + 1]);
    }
    float dmin[16];
#pragma unroll
    for (int j = 0; j < 16; ++j) dmin[j] = 1e10f;

    int last = 0;
    for (int it = 1; it < MM; ++it) {
        const float lx = sx[last], ly = sy[last], lz = sz[last];
        const ull nlx = bc2(-lx), nly = bc2(-ly), nlz = bc2(-lz);
        float bv = -1.0f; int bi = 0;
#pragma unroll
        for (int j = 0; j < 8; ++j) {
            ull s = sqdist2(X[j], Y[j], Z[j], nlx, nly, nlz);
            float d0, d1; unpack2(s, d0, d1);
            float m0 = fminf(dmin[2 * j + 0], d0); dmin[2 * j + 0] = m0;
            float m1 = fminf(dmin[2 * j + 1], d1); dmin[2 * j + 1] = m1;
            if (m0 > bv) { bv = m0; bi = base + 2 * j; }
            if (m1 > bv) { bv = m1; bi = base + 2 * j + 1; }
        }
        const unsigned bvb = __float_as_uint(bv);
        const unsigned mx  = __reduce_max_sync(0xffffffffu, bvb);
        const unsigned tie = __ballot_sync(0xffffffffu, bvb == mx);
        const int src = __ffs(tie) - 1;
        const int wbi = __shfl_sync(0xffffffffu, bi, src);

        const int p = it & 1;
        if (lane == 0)
            skey[p][tid >> 5] = (((ull)mx) << 32) | (unsigned)(4095 - wbi);
        __syncthreads();
        const ulonglong2* sk = reinterpret_cast<const ulonglong2*>(skey[p]);
        ulonglong2 a = sk[0], c = sk[1], d = sk[2], e = sk[3];
        ull m = umax64(umax64(umax64(a.x, a.y), umax64(c.x, c.y)),
                       umax64(umax64(d.x, d.y), umax64(e.x, e.y)));
        last = 4095 - (int)(m & 0xFFFFull);
        if (tid == 0) g_fps[b * MM + it] = last;
    }
}

// ---------------- Kernel B: ball query + exact top-64 threshold selection ----------------
// grid (64 chunks, 8 batches), 256 threads (8 warps), warp handles 2 centroids.
// Selection: the 64 smallest (d2,idx) keys. Since g_nbr feeds an order-invariant
// max-aggregation, only SET membership matters: binary-search the d2-bit threshold,
// take all d2 < d*, fill remaining slots with the lowest-index ties (buf is built
// in ascending-index order, so ballot-prefix order == index order: exact).
#define BCAP 512
__global__ void ballq_kernel(const float* __restrict__ pos) {
    extern __shared__ float sm[];
    float2* spx = (float2*)sm;
    float2* spy = spx + 2048;
    float2* spz = spy + 2048;
    ull* bufAll = (ull*)(spz + 2048);

    const int b = blockIdx.y;
    const int chunk = blockIdx.x;
    const int tid = threadIdx.x;
    const int warpId = tid >> 5;
    const int lane = tid & 31;
    const unsigned lanelt = (1u << lane) - 1u;
    const float* pb = pos + (size_t)b * NN * 3;

    for (int k = tid; k < NN * 3; k += 256) {
        float f = pb[k];
        int i = k / 3, comp = k - 3 * i;
        float* dst = (comp == 0) ? (float*)spx : (comp == 1) ? (float*)spy : (float*)spz;
        dst[(i & 2047) * 2 + (i >> 11)] = f;
    }
    __syncthreads();

    const ull* px = (const ull*)spx;
    const ull* py = (const ull*)spy;
    const ull* pz = (const ull*)spz;
    ull* buf = bufAll + (size_t)warpId * BCAP;
    const unsigned* bufHi = reinterpret_cast<const unsigned*>(buf);  // hi word at [2i+1]

    for (int cc = 0; cc < 2; ++cc) {
        const int c = chunk * 16 + warpId * 2 + cc;
        const int gi = g_fps[b * MM + c];
        const int hi2 = gi >> 11, ii = gi & 2047;
        float2 t;
        t = spx[ii]; const float cx = hi2 ? t.y : t.x;
        t = spy[ii]; const float cy = hi2 ? t.y : t.x;
        t = spz[ii]; const float cz = hi2 ? t.y : t.x;
        const ull ncx = bc2(-cx), ncy = bc2(-cy), ncz = bc2(-cz);

        int cnt = 0;
        for (int basej = 0; basej < 2048; basej += 32) {
            const int j = basej + lane;
            ull s = sqdist2(px[j], py[j], pz[j], ncx, ncy, ncz);
            float d0, d1; unpack2(s, d0, d1);
            bool in0 = (d0 <= R2F);
            unsigned m0 = __ballot_sync(0xffffffffu, in0);
            if (in0) {
                int off = cnt + __popc(m0 & lanelt);
                if (off < BCAP)
                    buf[off] = (((ull)__float_as_uint(d0)) << 32) | (unsigned)j;
            }
            cnt += __popc(m0);
            bool in1 = (d1 <= R2F);
            unsigned m1 = __ballot_sync(0xffffffffu, in1);
            if (in1) {
                int off = cnt + __popc(m1 & lanelt);
                if (off < BCAP)
                    buf[off] = (((ull)__float_as_uint(d1)) << 32) | (unsigned)(j + 2048);
            }
            cnt += __popc(m1);
        }
        int ccnt = min(cnt, BCAP);
        __syncwarp();
        int* outp = g_nbr + (size_t)(b * MM + c) * KNB;

        if (ccnt <= KNB) {
            for (int s2 = lane; s2 < KNB; s2 += 32) {
                int outi = (s2 < ccnt) ? (int)(buf[s2] & 0xffffffffull) : -1;
                outp[s2] = outi;
            }
            __syncwarp();
            continue;
        }

        // binary search threshold d* on d2 bits:
        // invariant: cntLess(lo) < 64 <= cntLess(hi)
        unsigned lo = 0u, hb = 0x3D23D70Cu;   // > bits(0.04f): cntLess(hb)=ccnt>=65
        while (hb - lo > 1u) {
            unsigned mid = (lo + hb) >> 1;
            int cl = 0;
            for (int i = lane; i < ccnt; i += 32)
                cl += (bufHi[2 * i + 1] < mid) ? 1 : 0;
            cl = __reduce_add_sync(0xffffffffu, cl);
            if (cl < KNB) lo = mid; else hb = mid;
        }
        const unsigned dstar = lo;
        int nless = 0;
        for (int i = lane; i < ccnt; i += 32)
            nless += (bufHi[2 * i + 1] < dstar) ? 1 : 0;
        nless = __reduce_add_sync(0xffffffffu, nless);
        const int need = KNB - nless;   // > 0; ties at dstar cover it

        int cum = 0, eqcum = 0;
        for (int basei = 0; basei < ccnt; basei += 32) {
            int i = basei + lane;
            bool has = (i < ccnt);
            unsigned db = has ? bufHi[2 * i + 1] : 0xFFFFFFFFu;
            bool lt = has && (db < dstar);
            bool eq = has && (db == dstar);
            unsigned eqm = __ballot_sync(0xffffffffu, eq);
            int eqrank = eqcum + __popc(eqm & lanelt);
            bool sel = lt || (eq && eqrank < need);
            unsigned sm_ = __ballot_sync(0xffffffffu, sel);
            if (sel)
                outp[cum + __popc(sm_ & lanelt)] = (int)(buf[i] & 0xffffffffull);
            cum += __popc(sm_);
            eqcum += __popc(eqm);
        }
        // cum == 64 exactly by construction
        __syncwarp();
    }
}

// ---------------- Kernel C: t = x @ W1[0:32,:] (unchanged) ----------------
__global__ void feat_kernel(const float* __restrict__ x, const float* __restrict__ W1) {
    __shared__ float Ws[CIN * 64];
    const int tid = threadIdx.x;
    for (int i = tid; i < CIN * 64; i += 256) Ws[i] = W1[i];
    __syncthreads();

    int g = blockIdx.x * 256 + tid;
    int p = g >> 2;
    int q = g & 3;

    float xr[32];
    const float4* xp = reinterpret_cast<const float4*>(x + (size_t)p * CIN);
#pragma unroll
    for (int k = 0; k < 8; ++k) {
        float4 v = xp[k];
        xr[4 * k + 0] = v.x; xr[4 * k + 1] = v.y; xr[4 * k + 2] = v.z; xr[4 * k + 3] = v.w;
    }
    float acc[16];
#pragma unroll
    for (int o = 0; o < 16; ++o) acc[o] = 0.0f;
#pragma unroll
    for (int i = 0; i < 32; ++i) {
        float xv = xr[i];
        const float4* wrow = reinterpret_cast<const float4*>(Ws + i * 64 + q * 16);
#pragma unroll
        for (int o4 = 0; o4 < 4; ++o4) {
            float4 w = wrow[o4];
            acc[o4 * 4 + 0] += xv * w.x;
            acc[o4 * 4 + 1] += xv * w.y;
            acc[o4 * 4 + 2] += xv * w.z;
            acc[o4 * 4 + 3] += xv * w.w;
        }
    }
    float4* tp = reinterpret_cast<float4*>(g_t + (size_t)p * 64 + q * 16);
#pragma unroll
    for (int o4 = 0; o4 < 4; ++o4)
        tp[o4] = make_float4(acc[o4 * 4 + 0], acc[o4 * 4 + 1], acc[o4 * 4 + 2], acc[o4 * 4 + 3]);
}

// ---------------- Kernel D v6: warp-per-centroid, weights in __constant__ ----------------
// 128 threads = 4 warps = 4 centroids, 2 neighbors/thread (lane, lane+32).
// Weight reads hit the constant port (uniform index), smem holds ONLY the H2 park
// (32KB) -> 3 blocks/SM. Accumulation order identical to v5: bit-exact.
#define C6_TOT  8192   /* floats: H2 park, [q 0..15][slot 0..1][tid 0..127] as ull */

__global__ void __launch_bounds__(128, 3) conv_kernel(
    const float* __restrict__ pos,
    float* __restrict__ out, int out_size)
{
    extern __shared__ float smf[];
    const int tid = threadIdx.x;

    const int warp = tid >> 5;
    const int lane = tid & 31;
    const int cid = blockIdx.x * 4 + warp;
    const int b = cid >> 10;

    const int gi = g_fps[cid];
    const float* pb = pos + (size_t)b * NN * 3;
    const float cx = pb[gi * 3 + 0], cy = pb[gi * 3 + 1], cz = pb[gi * 3 + 2];

    const int nj0 = g_nbr[(size_t)cid * KNB + lane];
    const int nj1 = g_nbr[(size_t)cid * KNB + lane + 32];
    const bool vld0 = (nj0 >= 0), vld1 = (nj1 >= 0);
    const int jj0 = vld0 ? nj0 : gi;
    const int jj1 = vld1 ? nj1 : gi;
    const float rx0 = pb[jj0 * 3 + 0] - cx, ry0 = pb[jj0 * 3 + 1] - cy, rz0 = pb[jj0 * 3 + 2] - cz;
    const float rx1 = pb[jj1 * 3 + 0] - cx, ry1 = pb[jj1 * 3 + 1] - cy, rz1 = pb[jj1 * 3 + 2] - cz;

    // ---- layer 1 for both neighbors ----
    float h0[64], h1[64];
    {
        const float4* tp0 = reinterpret_cast<const float4*>(g_t + ((size_t)b * NN + jj0) * 64);
        const float4* tp1 = reinterpret_cast<const float4*>(g_t + ((size_t)b * NN + jj1) * 64);
#pragma unroll
        for (int o4 = 0; o4 < 16; ++o4) {
            float4 bb  = reinterpret_cast<const float4*>(c_b1)[o4];
            float4 w0  = reinterpret_cast<const float4*>(c_W1p)[o4];
            float4 w1  = reinterpret_cast<const float4*>(c_W1p + 64)[o4];
            float4 w2v = reinterpret_cast<const float4*>(c_W1p + 128)[o4];
            float4 ta = tp0[o4];
            h0[4 * o4 + 0] = fmaxf(ta.x + bb.x + rx0 * w0.x + ry0 * w1.x + rz0 * w2v.x, 0.0f);
            h0[4 * o4 + 1] = fmaxf(ta.y + bb.y + rx0 * w0.y + ry0 * w1.y + rz0 * w2v.y, 0.0f);
            h0[4 * o4 + 2] = fmaxf(ta.z + bb.z + rx0 * w0.z + ry0 * w1.z + rz0 * w2v.z, 0.0f);
            h0[4 * o4 + 3] = fmaxf(ta.w + bb.w + rx0 * w0.w + ry0 * w1.w + rz0 * w2v.w, 0.0f);
            float4 tb = tp1[o4];
            h1[4 * o4 + 0] = fmaxf(tb.x + bb.x + rx1 * w0.x + ry1 * w1.x + rz1 * w2v.x, 0.0f);
            h1[4 * o4 + 1] = fmaxf(tb.y + bb.y + rx1 * w0.y + ry1 * w1.y + rz1 * w2v.y, 0.0f);
            h1[4 * o4 + 2] = fmaxf(tb.z + bb.z + rx1 * w0.z + ry1 * w1.z + rz1 * w2v.z, 0.0f);
            h1[4 * o4 + 3] = fmaxf(tb.w + bb.w + rx1 * w0.w + ry1 * w1.w + rz1 * w2v.w, 0.0f);
        }
    }

    ull* H2u = reinterpret_cast<ull*>(smf);
    const ull* b2u = reinterpret_cast<const ull*>(c_b2);

    // ---- layer 2: two 32-channel halves; one const weight load feeds both neighbors ----
#pragma unroll 1
    for (int hf = 0; hf < 2; ++hf) {
        ull acc0[16], acc1[16];
#pragma unroll
        for (int q = 0; q < 16; ++q) { ull bv = b2u[hf * 16 + q]; acc0[q] = bv; acc1[q] = bv; }
#pragma unroll 8
        for (int k = 0; k < 64; ++k) {
            ull hv0 = bc2(h0[k]);
            ull hv1 = bc2(h1[k]);
            const ulonglong2* wr = reinterpret_cast<const ulonglong2*>(c_W2 + k * 64 + hf * 32);
#pragma unroll
            for (int q = 0; q < 8; ++q) {
                ulonglong2 w = wr[q];
                fma2(acc0[2 * q + 0], hv0, w.x);
                fma2(acc0[2 * q + 1], hv0, w.y);
                fma2(acc1[2 * q + 0], hv1, w.x);
                fma2(acc1[2 * q + 1], hv1, w.y);
            }
        }
        if (hf == 0) {
#pragma unroll
            for (int q = 0; q < 16; ++q) {
                float lo, hi;
                unpack2(acc0[q], lo, hi);
                H2u[q * 256 + tid] = pack2(fmaxf(lo, 0.0f), fmaxf(hi, 0.0f));
                unpack2(acc1[q], lo, hi);
                H2u[q * 256 + 128 + tid] = pack2(fmaxf(lo, 0.0f), fmaxf(hi, 0.0f));
            }
        } else {
#pragma unroll
            for (int q = 0; q < 16; ++q) {
                float lo, hi;
                unpack2(acc0[q], lo, hi);
                h0[32 + 2 * q + 0] = fmaxf(lo, 0.0f);
                h0[32 + 2 * q + 1] = fmaxf(hi, 0.0f);
                unpack2(acc1[q], lo, hi);
                h1[32 + 2 * q + 0] = fmaxf(lo, 0.0f);
                h1[32 + 2 * q + 1] = fmaxf(hi, 0.0f);
            }
#pragma unroll
            for (int q = 0; q < 16; ++q) {
                float lo, hi;
                unpack2(H2u[q * 256 + tid], lo, hi);
                h0[2 * q + 0] = lo; h0[2 * q + 1] = hi;
                unpack2(H2u[q * 256 + 128 + tid], lo, hi);
                h1[2 * q + 0] = lo; h1[2 * q + 1] = hi;
            }
        }
    }

    // ---- layer 3: 4 passes of 32 channels + masked max ----
    const ull* b3u = reinterpret_cast<const ull*>(c_b3);
#pragma unroll 1
    for (int p = 0; p < 4; ++p) {
        ull acc0[16], acc1[16];
#pragma unroll
        for (int q = 0; q < 16; ++q) { ull bv = b3u[p * 16 + q]; acc0[q] = bv; acc1[q] = bv; }
#pragma unroll 8
        for (int k = 0; k < 64; ++k) {
            ull hv0 = bc2(h0[k]);
            ull hv1 = bc2(h1[k]);
            const ulonglong2* wr = reinterpret_cast<const ulonglong2*>(c_W3 + k * 128 + p * 32);
#pragma unroll
            for (int q = 0; q < 8; ++q) {
                ulonglong2 w = wr[q];
                fma2(acc0[2 * q + 0], hv0, w.x);
                fma2(acc0[2 * q + 1], hv0, w.y);
                fma2(acc1[2 * q + 0], hv1, w.x);
                fma2(acc1[2 * q + 1], hv1, w.y);
            }
        }
        float v[32];
#pragma unroll
        for (int q = 0; q < 16; ++q) {
            float a, bq, c, d;
            unpack2(acc0[q], a, bq);
            unpack2(acc1[q], c, d);
            v[2 * q + 0] = fmaxf(vld0 ? a  : NEGV, vld1 ? c : NEGV);
            v[2 * q + 1] = fmaxf(vld0 ? bq : NEGV, vld1 ? d : NEGV);
        }
#pragma unroll
        for (int s = 16; s; s >>= 1) {
#pragma unroll
            for (int c2 = 0; c2 < 32; ++c2)
                v[c2] = fmaxf(v[c2], __shfl_xor_sync(0xffffffffu, v[c2], s));
        }
        if (lane == 0) {
            int base = cid * 128 + p * 32;
            if (base + 32 <= out_size) {
#pragma unroll
                for (int q4 = 0; q4 < 8; ++q4)
                    reinterpret_cast<float4*>(out + base)[q4] =
                        make_float4(v[4 * q4 + 0], v[4 * q4 + 1], v[4 * q4 + 2], v[4 * q4 + 3]);
            } else {
                for (int c2 = 0; c2 < 32; ++c2)
                    if (base + c2 < out_size) out[base + c2] = v[c2];
            }
        }
    }
}

// ---------------- Kernel E: pos_out + batch_out tails ----------------
__global__ void tail_kernel(const float* __restrict__ pos, float* __restrict__ out, int out_size) {
    int i = blockIdx.x * 256 + threadIdx.x;
    if (i >= BB * MM) return;
    int b = i >> 10;
    int gi = g_fps[i];
    const float* pb = pos + (size_t)b * NN * 3;
    const int OX = BB * MM * 128;
    const int OP = OX + BB * MM * 3;
    const int OT = OP + BB * MM;
    if (out_size >= OP) {
        out[OX + i * 3 + 0] = pb[gi * 3 + 0];
        out[OX + i * 3 + 1] = pb[gi * 3 + 1];
        out[OX + i * 3 + 2] = pb[gi * 3 + 2];
    }
    if (out_size >= OT) out[OP + i] = (float)b;
}

extern "C" void kernel_launch(void* const* d_in, const int* in_sizes, int n_in,
                              void* d_out, int out_size) {
    const float* x   = (const float*)d_in[0];
    const float* pos = (const float*)d_in[1];
    const float* W1  = (const float*)d_in[3];
    const float* b1  = (const float*)d_in[4];
    const float* W2  = (const float*)d_in[5];
    const float* b2  = (const float*)d_in[6];
    const float* W3  = (const float*)d_in[7];
    const float* b3  = (const float*)d_in[8];
    float* out = (float*)d_out;

    const int smA = 3 * NN * 4;                        // 49152
    const int smB = 3 * NN * 4 + 8 * BCAP * 8;         // 81920
    const int smD = C6_TOT * 4;                        // 32768

    cudaFuncSetAttribute(fps_kernel,   cudaFuncAttributeMaxDynamicSharedMemorySize, smA);
    cudaFuncSetAttribute(ballq_kernel, cudaFuncAttributeMaxDynamicSharedMemorySize, smB);
    cudaFuncSetAttribute(conv_kernel,  cudaFuncAttributeMaxDynamicSharedMemorySize, smD);
    cudaFuncSetAttribute(fps_kernel,   cudaFuncAttributePreferredSharedMemoryCarveout, 100);
    cudaFuncSetAttribute(ballq_kernel, cudaFuncAttributePreferredSharedMemoryCarveout, 100);
    cudaFuncSetAttribute(conv_kernel,  cudaFuncAttributePreferredSharedMemoryCarveout, 100);

    // Stage conv weights into constant memory (D2D async: graph-capturable)
    cudaMemcpyToSymbolAsync(c_W2,  W2,            64 * 64 * sizeof(float), 0, cudaMemcpyDeviceToDevice);
    cudaMemcpyToSymbolAsync(c_W3,  W3,            64 * 128 * sizeof(float), 0, cudaMemcpyDeviceToDevice);
    cudaMemcpyToSymbolAsync(c_W1p, W1 + CIN * 64, 192 * sizeof(float),      0, cudaMemcpyDeviceToDevice);
    cudaMemcpyToSymbolAsync(c_b1,  b1,            64 * sizeof(float),       0, cudaMemcpyDeviceToDevice);
    cudaMemcpyToSymbolAsync(c_b2,  b2,            64 * sizeof(float),       0, cudaMemcpyDeviceToDevice);
    cudaMemcpyToSymbolAsync(c_b3,  b3,            128 * sizeof(float),      0, cudaMemcpyDeviceToDevice);

    fps_kernel<<<BB, 256, smA>>>(pos);
    ballq_kernel<<<dim3(64, BB), 256, smB>>>(pos);
    feat_kernel<<<(BB * NN * 4) / 256, 256>>>(x, W1);
    conv_kernel<<<(BB * MM) / 4, 128, smD>>>(pos, out, out_size);
    tail_kernel<<<(BB * MM) / 256, 256>>>(pos, out, out_size);
}

// round 17
// speedup vs baseline: 1.5347x; 1.5347x over previous
#include <cuda_runtime.h>
#include <cuda_bf16.h>
#include <cstdint>

// Problem constants
#define BB   8
#define NN   4096
#define MM   1024
#define CIN  32
#define KNB  64
#define NEGV (-1e10f)
#define R2F  (0.04f)

// Scratch (device globals: allocation-free)
__device__ int   g_fps[BB * MM];
__device__ float g_t[(size_t)BB * NN * 64];
__device__ int   g_nbr[(size_t)BB * MM * KNB];

typedef unsigned long long ull;

// ---------------- helpers: packed f32x2 ----------------
__device__ __forceinline__ ull pack2(float lo, float hi) {
    ull r; asm("mov.b64 %0, {%1, %2};" : "=l"(r) : "f"(lo), "f"(hi)); return r;
}
__device__ __forceinline__ ull bc2(float v) {
    ull r; asm("mov.b64 %0, {%1, %1};" : "=l"(r) : "f"(v)); return r;
}
__device__ __forceinline__ void unpack2(ull v, float& lo, float& hi) {
    asm("mov.b64 {%0, %1}, %2;" : "=f"(lo), "=f"(hi) : "l"(v));
}
__device__ __forceinline__ void fma2(ull& acc, ull a, ull b) {
    asm("fma.rn.f32x2 %0, %1, %2, %0;" : "+l"(acc) : "l"(a), "l"(b));
}
__device__ __forceinline__ ull add2(ull a, ull b) {
    ull r; asm("add.rn.f32x2 %0, %1, %2;" : "=l"(r) : "l"(a), "l"(b)); return r;
}
__device__ __forceinline__ ull mul2(ull a, ull b) {
    ull r; asm("mul.rn.f32x2 %0, %1, %2;" : "=l"(r) : "l"(a), "l"(b)); return r;
}
// per-component identical to __fadd_rn(__fadd_rn(__fmul_rn,__fmul_rn),__fmul_rn)
__device__ __forceinline__ ull sqdist2(ull X, ull Y, ull Z, ull ncx, ull ncy, ull ncz) {
    ull dx = add2(X, ncx), dy = add2(Y, ncy), dz = add2(Z, ncz);
    return add2(add2(mul2(dx, dx), mul2(dy, dy)), mul2(dz, dz));
}
__device__ __forceinline__ ull umax64(ull a, ull b) { return a > b ? a : b; }

// ---------------- Kernel A: farthest point sampling (v4, unchanged) ----------------
__global__ void __launch_bounds__(256) fps_kernel(const float* __restrict__ pos) {
    extern __shared__ float sm[];
    float* sx = sm;
    float* sy = sm + NN;
    float* sz = sm + 2 * NN;
    __shared__ alignas(16) ull skey[2][8];

    const int b = blockIdx.x;
    const int tid = threadIdx.x;
    const int lane = tid & 31;
    const float* pb = pos + (size_t)b * NN * 3;

    for (int i = tid; i < NN; i += 256) {
        sx[i] = pb[i * 3 + 0];
        sy[i] = pb[i * 3 + 1];
        sz[i] = pb[i * 3 + 2];
    }
    if (tid == 0) g_fps[b * MM] = 0;
    __syncthreads();

    const int base = tid * 16;
    ull X[8], Y[8], Z[8];
#pragma unroll
    for (int j = 0; j < 8; ++j) {
        X[j] = pack2(sx[base + 2 * j], sx[base + 2 * j + 1]);
        Y[j] = pack2(sy[base + 2 * j], sy[base + 2 * j + 1]);
        Z[j] = pack2(sz[base + 2 * j], sz[base + 2 * j + 1]);
    }
    float dmin[16];
#pragma unroll
    for (int j = 0; j < 16; ++j) dmin[j] = 1e10f;

    int last = 0;
    for (int it = 1; it < MM; ++it) {
        const float lx = sx[last], ly = sy[last], lz = sz[last];
        const ull nlx = bc2(-lx), nly = bc2(-ly), nlz = bc2(-lz);
        float bv = -1.0f; int bi = 0;
#pragma unroll
        for (int j = 0; j < 8; ++j) {
            ull s = sqdist2(X[j], Y[j], Z[j], nlx, nly, nlz);
            float d0, d1; unpack2(s, d0, d1);
            float m0 = fminf(dmin[2 * j + 0], d0); dmin[2 * j + 0] = m0;
            float m1 = fminf(dmin[2 * j + 1], d1); dmin[2 * j + 1] = m1;
            if (m0 > bv) { bv = m0; bi = base + 2 * j; }
            if (m1 > bv) { bv = m1; bi = base + 2 * j + 1; }
        }
        const unsigned bvb = __float_as_uint(bv);
        const unsigned mx  = __reduce_max_sync(0xffffffffu, bvb);
        const unsigned tie = __ballot_sync(0xffffffffu, bvb == mx);
        const int src = __ffs(tie) - 1;
        const int wbi = __shfl_sync(0xffffffffu, bi, src);

        const int p = it & 1;
        if (lane == 0)
            skey[p][tid >> 5] = (((ull)mx) << 32) | (unsigned)(4095 - wbi);
        __syncthreads();
        const ulonglong2* sk = reinterpret_cast<const ulonglong2*>(skey[p]);
        ulonglong2 a = sk[0], c = sk[1], d = sk[2], e = sk[3];
        ull m = umax64(umax64(umax64(a.x, a.y), umax64(c.x, c.y)),
                       umax64(umax64(d.x, d.y), umax64(e.x, e.y)));
        last = 4095 - (int)(m & 0xFFFFull);
        if (tid == 0) g_fps[b * MM + it] = last;
    }
}

// ---------------- Kernel B: ball query + bitonic top-64 (R15 proven version) ----------------
#define BCAP 512
__global__ void ballq_kernel(const float* __restrict__ pos) {
    extern __shared__ float sm[];
    float2* spx = (float2*)sm;
    float2* spy = spx + 2048;
    float2* spz = spy + 2048;
    ull* bufAll = (ull*)(spz + 2048);

    const int b = blockIdx.y;
    const int chunk = blockIdx.x;
    const int tid = threadIdx.x;
    const int warpId = tid >> 5;
    const int lane = tid & 31;
    const unsigned lanelt = (1u << lane) - 1u;
    const float* pb = pos + (size_t)b * NN * 3;

    for (int k = tid; k < NN * 3; k += 256) {
        float f = pb[k];
        int i = k / 3, comp = k - 3 * i;
        float* dst = (comp == 0) ? (float*)spx : (comp == 1) ? (float*)spy : (float*)spz;
        dst[(i & 2047) * 2 + (i >> 11)] = f;
    }
    __syncthreads();

    const ull* px = (const ull*)spx;
    const ull* py = (const ull*)spy;
    const ull* pz = (const ull*)spz;
    ull* buf = bufAll + (size_t)warpId * BCAP;

    for (int cc = 0; cc < 2; ++cc) {
        const int c = chunk * 16 + warpId * 2 + cc;
        const int gi = g_fps[b * MM + c];
        const int hi = gi >> 11, ii = gi & 2047;
        float2 t;
        t = spx[ii]; const float cx = hi ? t.y : t.x;
        t = spy[ii]; const float cy = hi ? t.y : t.x;
        t = spz[ii]; const float cz = hi ? t.y : t.x;
        const ull ncx = bc2(-cx), ncy = bc2(-cy), ncz = bc2(-cz);

        int cnt = 0;
        for (int basej = 0; basej < 2048; basej += 32) {
            const int j = basej + lane;
            ull s = sqdist2(px[j], py[j], pz[j], ncx, ncy, ncz);
            float d0, d1; unpack2(s, d0, d1);
            bool in0 = (d0 <= R2F);
            unsigned m0 = __ballot_sync(0xffffffffu, in0);
            if (in0) {
                int off = cnt + __popc(m0 & lanelt);
                if (off < BCAP)
                    buf[off] = (((ull)__float_as_uint(d0)) << 32) | (unsigned)j;
            }
            cnt += __popc(m0);
            bool in1 = (d1 <= R2F);
            unsigned m1 = __ballot_sync(0xffffffffu, in1);
            if (in1) {
                int off = cnt + __popc(m1 & lanelt);
                if (off < BCAP)
                    buf[off] = (((ull)__float_as_uint(d1)) << 32) | (unsigned)(j + 2048);
            }
            cnt += __popc(m1);
        }
        int ccnt = min(cnt, BCAP);
        __syncwarp();
        if (ccnt > KNB) {
            int n = KNB;
            while (n < ccnt) n <<= 1;
            for (int i = ccnt + lane; i < n; i += 32) buf[i] = 0xffffffffffffffffull;
            __syncwarp();
            for (int k2 = 2; k2 <= n; k2 <<= 1) {
                for (int j2 = k2 >> 1; j2 > 0; j2 >>= 1) {
                    for (int i = lane; i < n; i += 32) {
                        int ixj = i ^ j2;
                        if (ixj > i) {
                            ull a = buf[i], q = buf[ixj];
                            bool up = ((i & k2) == 0);
                            if ((a > q) == up) { buf[i] = q; buf[ixj] = a; }
                        }
                    }
                    __syncwarp();
                }
            }
        }
        int nv = min(ccnt, KNB);
        for (int s2 = lane; s2 < KNB; s2 += 32) {
            int outi = (s2 < nv) ? (int)(buf[s2] & 0xffffffffull) : -1;
            g_nbr[((size_t)(b * MM + c)) * KNB + s2] = outi;
        }
        __syncwarp();
    }
}

// ---------------- Kernel C: t = x @ W1[0:32,:] (unchanged) ----------------
__global__ void feat_kernel(const float* __restrict__ x, const float* __restrict__ W1) {
    __shared__ float Ws[CIN * 64];
    const int tid = threadIdx.x;
    for (int i = tid; i < CIN * 64; i += 256) Ws[i] = W1[i];
    __syncthreads();

    int g = blockIdx.x * 256 + tid;
    int p = g >> 2;
    int q = g & 3;

    float xr[32];
    const float4* xp = reinterpret_cast<const float4*>(x + (size_t)p * CIN);
#pragma unroll
    for (int k = 0; k < 8; ++k) {
        float4 v = xp[k];
        xr[4 * k + 0] = v.x; xr[4 * k + 1] = v.y; xr[4 * k + 2] = v.z; xr[4 * k + 3] = v.w;
    }
    float acc[16];
#pragma unroll
    for (int o = 0; o < 16; ++o) acc[o] = 0.0f;
#pragma unroll
    for (int i = 0; i < 32; ++i) {
        float xv = xr[i];
        const float4* wrow = reinterpret_cast<const float4*>(Ws + i * 64 + q * 16);
#pragma unroll
        for (int o4 = 0; o4 < 4; ++o4) {
            float4 w = wrow[o4];
            acc[o4 * 4 + 0] += xv * w.x;
            acc[o4 * 4 + 1] += xv * w.y;
            acc[o4 * 4 + 2] += xv * w.z;
            acc[o4 * 4 + 3] += xv * w.w;
        }
    }
    float4* tp = reinterpret_cast<float4*>(g_t + (size_t)p * 64 + q * 16);
#pragma unroll
    for (int o4 = 0; o4 < 4; ++o4)
        tp[o4] = make_float4(acc[o4 * 4 + 0], acc[o4 * 4 + 1], acc[o4 * 4 + 2], acc[o4 * 4 + 3]);
}

// ---------------- Kernel D v5b: warp-per-centroid, smem weights, 3 blocks/SM ----------------
// Same structure/arithmetic as v5 (proven bit-exact). H2 park shrunk 32KB->24KB:
// q-slots 0..11 go to smem, q-slots 12..15 stay in registers (+16 regs), so
// smem = 74.9KB <= 228/3 and launch_bounds(128,3) gives 12 warps/SM (was 8).
#define C5_W2   0        /* 4096 floats */
#define C5_W3   4096     /* 8192 */
#define C5_W1P  12288    /* 192  */
#define C5_B1   12480    /* 64   */
#define C5_B2   12544    /* 64   */
#define C5_B3   12608    /* 128  */
#define C5_H2   12736    /* 6144 floats = 3072 ull: [q 0..11][slot 0..1][tid 0..127] */
#define C5_TOT  18880

__global__ void __launch_bounds__(128, 3) conv_kernel(
    const float* __restrict__ pos,
    const float* __restrict__ W1, const float* __restrict__ b1,
    const float* __restrict__ W2, const float* __restrict__ b2,
    const float* __restrict__ W3, const float* __restrict__ b3,
    float* __restrict__ out, int out_size)
{
    extern __shared__ float smf[];
    const int tid = threadIdx.x;

    for (int i = tid; i < 4096; i += 128) smf[C5_W2 + i] = W2[i];
    for (int i = tid; i < 8192; i += 128) smf[C5_W3 + i] = W3[i];
    for (int i = tid; i < 192; i += 128)  smf[C5_W1P + i] = W1[CIN * 64 + i];
    if (tid < 64) smf[C5_B1 + tid] = b1[tid];
    if (tid < 64) smf[C5_B2 + tid] = b2[tid];
    smf[C5_B3 + tid] = b3[tid];
    __syncthreads();

    const int warp = tid >> 5;
    const int lane = tid & 31;
    const int cid = blockIdx.x * 4 + warp;
    const int b = cid >> 10;

    const int gi = g_fps[cid];
    const float* pb = pos + (size_t)b * NN * 3;
    const float cx = pb[gi * 3 + 0], cy = pb[gi * 3 + 1], cz = pb[gi * 3 + 2];

    const int nj0 = g_nbr[(size_t)cid * KNB + lane];
    const int nj1 = g_nbr[(size_t)cid * KNB + lane + 32];
    const bool vld0 = (nj0 >= 0), vld1 = (nj1 >= 0);
    const int jj0 = vld0 ? nj0 : gi;
    const int jj1 = vld1 ? nj1 : gi;
    const float rx0 = pb[jj0 * 3 + 0] - cx, ry0 = pb[jj0 * 3 + 1] - cy, rz0 = pb[jj0 * 3 + 2] - cz;
    const float rx1 = pb[jj1 * 3 + 0] - cx, ry1 = pb[jj1 * 3 + 1] - cy, rz1 = pb[jj1 * 3 + 2] - cz;

    // ---- layer 1 for both neighbors ----
    float h0[64], h1[64];
    {
        const float4* tp0 = reinterpret_cast<const float4*>(g_t + ((size_t)b * NN + jj0) * 64);
        const float4* tp1 = reinterpret_cast<const float4*>(g_t + ((size_t)b * NN + jj1) * 64);
#pragma unroll
        for (int o4 = 0; o4 < 16; ++o4) {
            float4 bb  = reinterpret_cast<const float4*>(smf + C5_B1)[o4];
            float4 w0  = reinterpret_cast<const float4*>(smf + C5_W1P)[o4];
            float4 w1  = reinterpret_cast<const float4*>(smf + C5_W1P + 64)[o4];
            float4 w2v = reinterpret_cast<const float4*>(smf + C5_W1P + 128)[o4];
            float4 ta = tp0[o4];
            h0[4 * o4 + 0] = fmaxf(ta.x + bb.x + rx0 * w0.x + ry0 * w1.x + rz0 * w2v.x, 0.0f);
            h0[4 * o4 + 1] = fmaxf(ta.y + bb.y + rx0 * w0.y + ry0 * w1.y + rz0 * w2v.y, 0.0f);
            h0[4 * o4 + 2] = fmaxf(ta.z + bb.z + rx0 * w0.z + ry0 * w1.z + rz0 * w2v.z, 0.0f);
            h0[4 * o4 + 3] = fmaxf(ta.w + bb.w + rx0 * w0.w + ry0 * w1.w + rz0 * w2v.w, 0.0f);
            float4 tb = tp1[o4];
            h1[4 * o4 + 0] = fmaxf(tb.x + bb.x + rx1 * w0.x + ry1 * w1.x + rz1 * w2v.x, 0.0f);
            h1[4 * o4 + 1] = fmaxf(tb.y + bb.y + rx1 * w0.y + ry1 * w1.y + rz1 * w2v.y, 0.0f);
            h1[4 * o4 + 2] = fmaxf(tb.z + bb.z + rx1 * w0.z + ry1 * w1.z + rz1 * w2v.z, 0.0f);
            h1[4 * o4 + 3] = fmaxf(tb.w + bb.w + rx1 * w0.w + ry1 * w1.w + rz1 * w2v.w, 0.0f);
        }
    }

    ull* H2u = reinterpret_cast<ull*>(smf + C5_H2);
    const ull* b2u = reinterpret_cast<const ull*>(smf + C5_B2);
    ull keep0[4], keep1[4];   // q-slots 12..15 of half 0 (registers, not parked)

    // ---- layer 2: two 32-channel halves; one weight load feeds both neighbors ----
#pragma unroll 1
    for (int hf = 0; hf < 2; ++hf) {
        ull acc0[16], acc1[16];
#pragma unroll
        for (int q = 0; q < 16; ++q) { ull bv = b2u[hf * 16 + q]; acc0[q] = bv; acc1[q] = bv; }
#pragma unroll 8
        for (int k = 0; k < 64; ++k) {
            ull hv0 = bc2(h0[k]);
            ull hv1 = bc2(h1[k]);
            const ulonglong2* wr = reinterpret_cast<const ulonglong2*>(smf + C5_W2 + k * 64 + hf * 32);
#pragma unroll
            for (int q = 0; q < 8; ++q) {
                ulonglong2 w = wr[q];
                fma2(acc0[2 * q + 0], hv0, w.x);
                fma2(acc0[2 * q + 1], hv0, w.y);
                fma2(acc1[2 * q + 0], hv1, w.x);
                fma2(acc1[2 * q + 1], hv1, w.y);
            }
        }
        if (hf == 0) {
            // relu -> park q 0..11 in thread-private smem, q 12..15 in registers
#pragma unroll
            for (int q = 0; q < 12; ++q) {
                float lo, hi;
                unpack2(acc0[q], lo, hi);
                H2u[q * 256 + tid] = pack2(fmaxf(lo, 0.0f), fmaxf(hi, 0.0f));
                unpack2(acc1[q], lo, hi);
                H2u[q * 256 + 128 + tid] = pack2(fmaxf(lo, 0.0f), fmaxf(hi, 0.0f));
            }
#pragma unroll
            for (int q = 12; q < 16; ++q) {
                float lo, hi;
                unpack2(acc0[q], lo, hi);
                keep0[q - 12] = pack2(fmaxf(lo, 0.0f), fmaxf(hi, 0.0f));
                unpack2(acc1[q], lo, hi);
                keep1[q - 12] = pack2(fmaxf(lo, 0.0f), fmaxf(hi, 0.0f));
            }
        } else {
#pragma unroll
            for (int q = 0; q < 16; ++q) {
                float lo, hi;
                unpack2(acc0[q], lo, hi);
                h0[32 + 2 * q + 0] = fmaxf(lo, 0.0f);
                h0[32 + 2 * q + 1] = fmaxf(hi, 0.0f);
                unpack2(acc1[q], lo, hi);
                h1[32 + 2 * q + 0] = fmaxf(lo, 0.0f);
                h1[32 + 2 * q + 1] = fmaxf(hi, 0.0f);
            }
#pragma unroll
            for (int q = 0; q < 12; ++q) {
                float lo, hi;
                unpack2(H2u[q * 256 + tid], lo, hi);
                h0[2 * q + 0] = lo; h0[2 * q + 1] = hi;
                unpack2(H2u[q * 256 + 128 + tid], lo, hi);
                h1[2 * q + 0] = lo; h1[2 * q + 1] = hi;
            }
#pragma unroll
            for (int q = 12; q < 16; ++q) {
                float lo, hi;
                unpack2(keep0[q - 12], lo, hi);
                h0[2 * q + 0] = lo; h0[2 * q + 1] = hi;
                unpack2(keep1[q - 12], lo, hi);
                h1[2 * q + 0] = lo; h1[2 * q + 1] = hi;
            }
        }
    }

    // ---- layer 3: 4 passes of 32 channels + masked max ----
    const ull* b3u = reinterpret_cast<const ull*>(smf + C5_B3);
#pragma unroll 1
    for (int p = 0; p < 4; ++p) {
        ull acc0[16], acc1[16];
#pragma unroll
        for (int q = 0; q < 16; ++q) { ull bv = b3u[p * 16 + q]; acc0[q] = bv; acc1[q] = bv; }
#pragma unroll 8
        for (int k = 0; k < 64; ++k) {
            ull hv0 = bc2(h0[k]);
            ull hv1 = bc2(h1[k]);
            const ulonglong2* wr = reinterpret_cast<const ulonglong2*>(smf + C5_W3 + k * 128 + p * 32);
#pragma unroll
            for (int q = 0; q < 8; ++q) {
                ulonglong2 w = wr[q];
                fma2(acc0[2 * q + 0], hv0, w.x);
                fma2(acc0[2 * q + 1], hv0, w.y);
                fma2(acc1[2 * q + 0], hv1, w.x);
                fma2(acc1[2 * q + 1], hv1, w.y);
            }
        }
        float v[32];
#pragma unroll
        for (int q = 0; q < 16; ++q) {
            float a, bq, c, d;
            unpack2(acc0[q], a, bq);
            unpack2(acc1[q], c, d);
            v[2 * q + 0] = fmaxf(vld0 ? a  : NEGV, vld1 ? c : NEGV);
            v[2 * q + 1] = fmaxf(vld0 ? bq : NEGV, vld1 ? d : NEGV);
        }
#pragma unroll
        for (int s = 16; s; s >>= 1) {
#pragma unroll
            for (int c2 = 0; c2 < 32; ++c2)
                v[c2] = fmaxf(v[c2], __shfl_xor_sync(0xffffffffu, v[c2], s));
        }
        if (lane == 0) {
            int base = cid * 128 + p * 32;
            if (base + 32 <= out_size) {
#pragma unroll
                for (int q4 = 0; q4 < 8; ++q4)
                    reinterpret_cast<float4*>(out + base)[q4] =
                        make_float4(v[4 * q4 + 0], v[4 * q4 + 1], v[4 * q4 + 2], v[4 * q4 + 3]);
            } else {
                for (int c2 = 0; c2 < 32; ++c2)
                    if (base + c2 < out_size) out[base + c2] = v[c2];
            }
        }
    }
}

// ---------------- Kernel E: pos_out + batch_out tails ----------------
__global__ void tail_kernel(const float* __restrict__ pos, float* __restrict__ out, int out_size) {
    int i = blockIdx.x * 256 + threadIdx.x;
    if (i >= BB * MM) return;
    int b = i >> 10;
    int gi = g_fps[i];
    const float* pb = pos + (size_t)b * NN * 3;
    const int OX = BB * MM * 128;
    const int OP = OX + BB * MM * 3;
    const int OT = OP + BB * MM;
    if (out_size >= OP) {
        out[OX + i * 3 + 0] = pb[gi * 3 + 0];
        out[OX + i * 3 + 1] = pb[gi * 3 + 1];
        out[OX + i * 3 + 2] = pb[gi * 3 + 2];
    }
    if (out_size >= OT) out[OP + i] = (float)b;
}

extern "C" void kernel_launch(void* const* d_in, const int* in_sizes, int n_in,
                              void* d_out, int out_size) {
    const float* x   = (const float*)d_in[0];
    const float* pos = (const float*)d_in[1];
    const float* W1  = (const float*)d_in[3];
    const float* b1  = (const float*)d_in[4];
    const float* W2  = (const float*)d_in[5];
    const float* b2  = (const float*)d_in[6];
    const float* W3  = (const float*)d_in[7];
    const float* b3  = (const float*)d_in[8];
    float* out = (float*)d_out;

    const int smA = 3 * NN * 4;                        // 49152
    const int smB = 3 * NN * 4 + 8 * BCAP * 8;         // 81920
    const int smD = C5_TOT * 4;                        // 75520

    cudaFuncSetAttribute(fps_kernel,   cudaFuncAttributeMaxDynamicSharedMemorySize, smA);
    cudaFuncSetAttribute(ballq_kernel, cudaFuncAttributeMaxDynamicSharedMemorySize, smB);
    cudaFuncSetAttribute(conv_kernel,  cudaFuncAttributeMaxDynamicSharedMemorySize, smD);
    cudaFuncSetAttribute(fps_kernel,   cudaFuncAttributePreferredSharedMemoryCarveout, 100);
    cudaFuncSetAttribute(ballq_kernel, cudaFuncAttributePreferredSharedMemoryCarveout, 100);
    cudaFuncSetAttribute(conv_kernel,  cudaFuncAttributePreferredSharedMemoryCarveout, 100);

    fps_kernel<<<BB, 256, smA>>>(pos);
    ballq_kernel<<<dim3(64, BB), 256, smB>>>(pos);
    feat_kernel<<<(BB * NN * 4) / 256, 256>>>(x, W1);
    conv_kernel<<<(BB * MM) / 4, 128, smD>>>(pos, W1, b1, W2, b2, W3, b3, out, out_size);
    tail_kernel<<<(BB * MM) / 256, 256>>>(pos, out, out_size);
}